// round 5
// baseline (speedup 1.0000x reference)
#include <cuda_runtime.h>
#include <cuda_bf16.h>

#define NBIN 25
#define DELTA (2.0f / (NBIN - 1))
#define INV_DELTA ((NBIN - 1) / 2.0f)

// Per-batch accumulators: num[bin], den[bin], label-sum.
// Sized 32 so lane 25 (f==0 edge writes to bin k0+1==25) lands harmlessly in-bounds.
__device__ float g_num[16][32];
__device__ float g_den[16][32];
__device__ float g_lab[16];

__global__ void qap_zero_kernel() {
    int t = threadIdx.x;
    if (t < 16 * 32) {
        ((float*)g_num)[t] = 0.0f;
        ((float*)g_den)[t] = 0.0f;
    }
    if (t < 16) g_lab[t] = 0.0f;
}

__global__ __launch_bounds__(256) void qap_main_kernel(
    const float* __restrict__ qX,
    const float* __restrict__ dXs,
    const int* __restrict__ labels,
    int N)
{
    const int b = blockIdx.y;
    const int lane = threadIdx.x & 31;
    const int warp = threadIdx.x >> 5;
    const int warps_per_b = gridDim.x * (blockDim.x >> 5);
    const int wid = blockIdx.x * (blockDim.x >> 5) + warp;

    // Query vector: lane owns 4 of 128 elements (one float4).
    float4 q = reinterpret_cast<const float4*>(qX + (long)b * 128)[lane];

    // ||q|| once per warp.
    float qq = q.x * q.x + q.y * q.y + q.z * q.z + q.w * q.w;
    #pragma unroll
    for (int o = 16; o; o >>= 1) qq += __shfl_xor_sync(0xFFFFFFFFu, qq, o);
    float qinv = 1.0f / fmaxf(sqrtf(qq), 1e-8f);

    const float4* __restrict__ base =
        reinterpret_cast<const float4*>(dXs) + ((long)b * N) * 32;
    const int* __restrict__ lab_b = labels + (long)b * N;

    // Lane-private bin accumulators: lane l owns bin l (lanes >= 26 contribute 0).
    float num_acc = 0.0f, den_acc = 0.0f, lab_acc = 0.0f;

    for (int n = wid; n < N; n += 2 * warps_per_b) {
        const int n2 = n + warps_per_b;
        const bool has2 = (n2 < N);

        // Two independent row loads in flight -> MLP / latency hiding.
        float4 d1 = base[(long)n * 32 + lane];
        float4 d2 = has2 ? base[(long)n2 * 32 + lane]
                         : make_float4(0.f, 0.f, 0.f, 0.f);
        int l1 = lab_b[n];
        int l2 = has2 ? lab_b[n2] : 0;

        float dot1 = d1.x * q.x + d1.y * q.y + d1.z * q.z + d1.w * q.w;
        float dd1  = d1.x * d1.x + d1.y * d1.y + d1.z * d1.z + d1.w * d1.w;
        float dot2 = d2.x * q.x + d2.y * q.y + d2.z * q.z + d2.w * q.w;
        float dd2  = d2.x * d2.x + d2.y * d2.y + d2.z * d2.z + d2.w * d2.w;

        // Four interleaved butterfly chains (independent -> issue-pipelined).
        #pragma unroll
        for (int o = 16; o; o >>= 1) {
            dot1 += __shfl_xor_sync(0xFFFFFFFFu, dot1, o);
            dot2 += __shfl_xor_sync(0xFFFFFFFFu, dot2, o);
            dd1  += __shfl_xor_sync(0xFFFFFFFFu, dd1,  o);
            dd2  += __shfl_xor_sync(0xFFFFFFFFu, dd2,  o);
        }

        // Row 1: triangular soft-assignment hits exactly bins k0, k0+1.
        {
            float sim = dot1 * qinv * rsqrtf(fmaxf(dd1, 1e-16f));
            float t = (1.0f - sim) * INV_DELTA;
            t = fminf(fmaxf(t, 0.0f), (float)(NBIN - 1));
            int k0 = (int)t;
            float f = t - (float)k0;
            float lbl = (float)l1;
            float w = (lane == k0) ? (1.0f - f) : ((lane == k0 + 1) ? f : 0.0f);
            den_acc += w;
            num_acc += w * lbl;
            lab_acc += lbl;
        }
        // Row 2 (tail-guarded).
        if (has2) {
            float sim = dot2 * qinv * rsqrtf(fmaxf(dd2, 1e-16f));
            float t = (1.0f - sim) * INV_DELTA;
            t = fminf(fmaxf(t, 0.0f), (float)(NBIN - 1));
            int k0 = (int)t;
            float f = t - (float)k0;
            float lbl = (float)l2;
            float w = (lane == k0) ? (1.0f - f) : ((lane == k0 + 1) ? f : 0.0f);
            den_acc += w;
            num_acc += w * lbl;
            lab_acc += lbl;
        }
    }

    // Flush per-warp partials: 26 float atomics per warp (negligible traffic).
    if (lane < 26) {
        atomicAdd(&g_num[b][lane], num_acc);
        atomicAdd(&g_den[b][lane], den_acc);
    }
    if (lane == 0) atomicAdd(&g_lab[b], lab_acc);
}

__global__ void qap_final_kernel(float* __restrict__ out) {
    int b = threadIdx.x;  // one warp; thread b handles batch b
    float ap = 0.0f;
    if (b < 16) {
        float labsum = g_lab[b];
        float cum_num = 0.0f;
        float cum_den = 1e-16f;     // EPS_P seed, matches reference pNum init
        #pragma unroll
        for (int k = 0; k < NBIN; k++) {
            float nb = g_num[b][k];
            float db = g_den[b][k];
            cum_num += nb;           // cumsum(num_per_bin) == pDen
            cum_den += db;           // EPS_P + cumsum(den_per_bin) == pNum
            float prec = cum_num / cum_den;
            float rec  = nb / labsum;
            ap += prec * rec;
        }
    }
    #pragma unroll
    for (int o = 16; o; o >>= 1) ap += __shfl_xor_sync(0xFFFFFFFFu, ap, o);
    if (threadIdx.x == 0) out[0] = ap * (1.0f / 16.0f);
}

extern "C" void kernel_launch(void* const* d_in, const int* in_sizes, int n_in,
                              void* d_out, int out_size) {
    const float* qX   = (const float*)d_in[0];
    const float* dXs  = (const float*)d_in[1];
    const int*   labs = (const int*)d_in[2];
    float* out = (float*)d_out;

    const int B = in_sizes[0] / 128;     // 16
    const int N = in_sizes[2] / B;       // 50000

    qap_zero_kernel<<<1, 512>>>();

    dim3 grid(74, B, 1);                 // 74*16 = 1184 blocks = 8/SM, 64 warps/SM
    qap_main_kernel<<<grid, 256>>>(qX, dXs, labs, N);

    qap_final_kernel<<<1, 32>>>(out);
}

// round 9
// speedup vs baseline: 1.0434x; 1.0434x over previous
#include <cuda_runtime.h>
#include <cuda_bf16.h>

#define NBIN 25
#define INV_DELTA 12.0f          // (NBIN-1)/2
#define GRIDX 74                 // blocks per batch

// Per-(batch, block) partials — every slot fully written by its owner block,
// so no zero-initialization kernel is needed (no atomics anywhere).
__device__ float gp_num[16][GRIDX][32];
__device__ float gp_den[16][GRIDX][32];
__device__ float gp_lab[16][GRIDX];

__global__ __launch_bounds__(256) void qap_main_kernel(
    const float* __restrict__ qX,
    const float* __restrict__ dXs,
    const int* __restrict__ labels,
    int N)
{
    __shared__ float4 s_q[32];
    __shared__ float  s_num[8][32];
    __shared__ float  s_den[8][32];
    __shared__ float  s_lab[8];

    const int b    = blockIdx.y;
    const int tid  = threadIdx.x;
    const int lane = tid & 31;
    const int warp = tid >> 5;
    const int g    = lane >> 2;   // row-within-chunk 0..7
    const int s    = lane & 3;    // quarter-group sub-lane 0..3

    if (tid < 32) s_q[tid] = reinterpret_cast<const float4*>(qX + (long)b * 128)[tid];
    __syncthreads();

    // ||q||^2 (identical summation order on every thread)
    float qq = 0.0f;
    #pragma unroll
    for (int i = 0; i < 32; i++) {
        float4 v = s_q[i];
        qq += v.x * v.x + v.y * v.y + v.z * v.z + v.w * v.w;
    }
    const float qinv = 1.0f / fmaxf(sqrtf(qq), 1e-8f);

    const float4* __restrict__ dbase =
        reinterpret_cast<const float4*>(dXs) + ((long)b * N) * 32;
    const int* __restrict__ lab_b = labels + (long)b * N;

    const int warps_per_b = GRIDX * 8;
    const int wid = blockIdx.x * 8 + warp;
    const int nchunks = N >> 3;           // full 8-row chunks
    const float lane_f = (float)lane;

    float num_acc = 0.0f, den_acc = 0.0f, lab_acc = 0.0f;

    for (int c = wid; c < nchunks; c += warps_per_b) {
        const long row = (long)c * 8 + g;
        const float4* __restrict__ rp = dbase + row * 32 + s;

        // 8 independent strided loads (chunk = 4KB contiguous, fully coalesced)
        float4 d[8];
        #pragma unroll
        for (int i = 0; i < 8; i++) d[i] = rp[4 * i];

        // label for this group's row (lanes 0,4,...,28 -> 8 consecutive ints)
        int li = 0;
        if (s == 0) li = lab_b[row];

        float dot = 0.0f, dd = 0.0f;
        #pragma unroll
        for (int i = 0; i < 8; i++) {
            float4 qi = s_q[s + 4 * i];
            dot += d[i].x * qi.x + d[i].y * qi.y + d[i].z * qi.z + d[i].w * qi.w;
            dd  += d[i].x * d[i].x + d[i].y * d[i].y + d[i].z * d[i].z + d[i].w * d[i].w;
        }

        // reduce within group of 4 lanes (2 stages, 4 shuffles per 8 rows)
        dot += __shfl_xor_sync(0xFFFFFFFFu, dot, 1);
        dd  += __shfl_xor_sync(0xFFFFFFFFu, dd,  1);
        dot += __shfl_xor_sync(0xFFFFFFFFu, dot, 2);
        dd  += __shfl_xor_sync(0xFFFFFFFFu, dd,  2);

        // sim -> bin position t in [0,24]; pack label into sign bit (t==0 safe: -0.0)
        float sim = dot * qinv * rsqrtf(fmaxf(dd, 1e-16f));
        float t = fminf(fmaxf((1.0f - sim) * INV_DELTA, 0.0f), 24.0f);
        float u = __uint_as_float(__float_as_uint(t) | (((unsigned)li) << 31));

        // 8 broadcasts: whole warp applies triangular weights; lane owns bin lane.
        // t<=24 guarantees lanes >=26 get w<=0 automatically.
        #pragma unroll
        for (int j = 0; j < 8; j++) {
            float uj = __shfl_sync(0xFFFFFFFFu, u, j * 4);
            unsigned ub = __float_as_uint(uj);
            float tj = __uint_as_float(ub & 0x7FFFFFFFu);
            float lj = (float)(ub >> 31);
            float w = fmaxf(1.0f - fabsf(tj - lane_f), 0.0f);
            den_acc += w;
            num_acc += w * lj;
            lab_acc += lj;          // same on all lanes; lane 0's copy is flushed
        }
    }

    // Tail rows (N % 8): classic warp-per-row on warp 0 only (dead for N=50000)
    if ((N & 7) && wid == 0) {
        float4 qv = s_q[lane];
        for (long r = (long)nchunks * 8; r < N; r++) {
            float4 dv = dbase[r * 32 + lane];
            float dot = dv.x * qv.x + dv.y * qv.y + dv.z * qv.z + dv.w * qv.w;
            float dd  = dv.x * dv.x + dv.y * dv.y + dv.z * dv.z + dv.w * dv.w;
            #pragma unroll
            for (int o = 16; o; o >>= 1) {
                dot += __shfl_xor_sync(0xFFFFFFFFu, dot, o);
                dd  += __shfl_xor_sync(0xFFFFFFFFu, dd,  o);
            }
            float lbl = (float)lab_b[r];
            float sim = dot * qinv * rsqrtf(fmaxf(dd, 1e-16f));
            float t = fminf(fmaxf((1.0f - sim) * INV_DELTA, 0.0f), 24.0f);
            float w = fmaxf(1.0f - fabsf(t - lane_f), 0.0f);
            den_acc += w;
            num_acc += w * lbl;
            lab_acc += lbl;
        }
    }

    // Block-level reduction of per-warp partials; deterministic, no atomics.
    s_num[warp][lane] = num_acc;
    s_den[warp][lane] = den_acc;
    if (lane == 0) s_lab[warp] = lab_acc;
    __syncthreads();

    if (warp == 0) {
        float n = 0.0f, dsum = 0.0f;
        #pragma unroll
        for (int w2 = 0; w2 < 8; w2++) {
            n    += s_num[w2][lane];
            dsum += s_den[w2][lane];
        }
        gp_num[b][blockIdx.x][lane] = n;
        gp_den[b][blockIdx.x][lane] = dsum;
        if (lane == 0) {
            float L = 0.0f;
            #pragma unroll
            for (int w2 = 0; w2 < 8; w2++) L += s_lab[w2];
            gp_lab[b][blockIdx.x] = L;
        }
    }
}

__global__ void qap_final_kernel(float* __restrict__ out) {
    __shared__ float s_ap[16];
    const int warp = threadIdx.x >> 5;   // one warp per batch (16 warps)
    const int lane = threadIdx.x & 31;
    const int b = warp;

    float n = 0.0f, d = 0.0f, L = 0.0f;
    for (int j = 0; j < GRIDX; j++) {
        n += gp_num[b][j][lane];
        d += gp_den[b][j][lane];
        L += gp_lab[b][j];
    }

    // inclusive scan across lanes (bins) for cumulative num/den
    float cn = n, cd = d;
    #pragma unroll
    for (int o = 1; o < 32; o <<= 1) {
        float vn = __shfl_up_sync(0xFFFFFFFFu, cn, o);
        float vd = __shfl_up_sync(0xFFFFFFFFu, cd, o);
        if (lane >= o) { cn += vn; cd += vd; }
    }

    float prec = cn / (1e-16f + cd);   // pDen / pNum
    float rec  = n / L;                // num_per_bin / sum(labels)
    float term = (lane < NBIN) ? prec * rec : 0.0f;
    #pragma unroll
    for (int o = 16; o; o >>= 1) term += __shfl_xor_sync(0xFFFFFFFFu, term, o);
    if (lane == 0) s_ap[b] = term;
    __syncthreads();

    if (threadIdx.x < 32) {
        float ap = (threadIdx.x < 16) ? s_ap[threadIdx.x] : 0.0f;
        #pragma unroll
        for (int o = 16; o; o >>= 1) ap += __shfl_xor_sync(0xFFFFFFFFu, ap, o);
        if (threadIdx.x == 0) out[0] = ap * (1.0f / 16.0f);
    }
}

extern "C" void kernel_launch(void* const* d_in, const int* in_sizes, int n_in,
                              void* d_out, int out_size) {
    const float* qX   = (const float*)d_in[0];
    const float* dXs  = (const float*)d_in[1];
    const int*   labs = (const int*)d_in[2];
    float* out = (float*)d_out;

    const int B = in_sizes[0] / 128;   // 16
    const int N = in_sizes[2] / B;     // 50000

    dim3 grid(GRIDX, B, 1);
    qap_main_kernel<<<grid, 256>>>(qX, dXs, labs, N);
    qap_final_kernel<<<1, 512>>>(out);
}